// round 5
// baseline (speedup 1.0000x reference)
#include <cuda_runtime.h>
#include <cuda_bf16.h>
#include <math.h>
#include <stdint.h>

#define H 1024
#define E 64
#define MAXN 32768
#define BM 128
#define AST 144u          // padded smem row stride (bytes): 64 bf16 + 16B pad
#define MAXSUS 8192

// smem layout (bytes)
#define SM_A_HI 0u
#define SM_A_LO 18432u
#define SM_B_HI 36864u
#define SM_B_LO 46080u
#define SMEM_BYTES 55296

// ---------------- scratch (no allocation allowed) ----------------
__device__ float         g_logits[(size_t)MAXN * E];   // logits -> probs (in place)
__device__ unsigned      g_keys[(size_t)MAXN * E];     // token-major mono keys (0 = unassigned)
__device__ unsigned      g_lists[(size_t)E * MAXN];    // per-expert compacted keys
__device__ int           g_cnt[E];
__device__ __align__(256) __nv_bfloat16 g_whi[E * H];
__device__ __align__(256) __nv_bfloat16 g_wlo[E * H];
__device__ unsigned      g_thresh[E];
__device__ float         g_fi[E];
__device__ float         g_pi[E];
__device__ int           g_nsus;
__device__ unsigned      g_sus[MAXSUS];

__device__ __forceinline__ unsigned mono_key(float f) {
    unsigned u = __float_as_uint(f);
    return (u & 0x80000000u) ? ~u : (u | 0x80000000u);
}

static __device__ __forceinline__ uint32_t smem_u32(const void* p) {
    uint32_t a;
    asm("{ .reg .u64 t; cvta.to.shared.u64 t, %1; cvt.u32.u64 %0, t; }" : "=r"(a) : "l"(p));
    return a;
}
static __device__ __forceinline__ void cp16(uint32_t dst, const void* src) {
    asm volatile("cp.async.ca.shared.global [%0], [%1], 16;" :: "r"(dst), "l"(src) : "memory");
}
static __device__ __forceinline__ void sts32(uint32_t addr, uint32_t v) {
    asm volatile("st.shared.b32 [%0], %1;" :: "r"(addr), "r"(v) : "memory");
}
static __device__ __forceinline__ void ldm_x4(uint32_t* r, uint32_t addr) {
    asm volatile("ldmatrix.sync.aligned.m8n8.x4.shared.b16 {%0,%1,%2,%3}, [%4];"
                 : "=r"(r[0]), "=r"(r[1]), "=r"(r[2]), "=r"(r[3]) : "r"(addr));
}
static __device__ __forceinline__ void mma16816(float* c, const uint32_t* a, const uint32_t* b) {
    asm volatile("mma.sync.aligned.m16n8k16.row.col.f32.bf16.bf16.f32 "
                 "{%0,%1,%2,%3}, {%4,%5,%6,%7}, {%8,%9}, {%0,%1,%2,%3};"
                 : "+f"(c[0]), "+f"(c[1]), "+f"(c[2]), "+f"(c[3])
                 : "r"(a[0]), "r"(a[1]), "r"(a[2]), "r"(a[3]), "r"(b[0]), "r"(b[1]));
}
static __device__ __forceinline__ void cvt_split(float a, float b, uint32_t& hi, uint32_t& lo) {
    __nv_bfloat162 h = __floats2bfloat162_rn(a, b);
    hi = *reinterpret_cast<uint32_t*>(&h);
    __nv_bfloat162 l = __floats2bfloat162_rn(a - __low2float(h), b - __high2float(h));
    lo = *reinterpret_cast<uint32_t*>(&l);
}

// ---------------- init ----------------
__global__ void init_kernel() {
    int t = threadIdx.x;
    if (t < E) { g_fi[t] = 0.f; g_pi[t] = 0.f; g_cnt[t] = 0; }
    if (t == 0) g_nsus = 0;
}

// ---------------- convert gate_w to bf16 hi/lo ----------------
__global__ __launch_bounds__(256) void convert_w_kernel(const float* __restrict__ w) {
    int i = blockIdx.x * blockDim.x + threadIdx.x;
    if (i < E * H) {
        float v = w[i];
        __nv_bfloat16 h = __float2bfloat16(v);
        g_whi[i] = h;
        g_wlo[i] = __float2bfloat16(v - __bfloat162float(h));
    }
}

// ---------------- HMMA GEMM: 128 tokens x 64 experts / block, 3-pass bf16 split ----------------
__global__ __launch_bounds__(256, 2) void gemm_mma_kernel(const float* __restrict__ x) {
    extern __shared__ __align__(16) char smem[];
    uint32_t sb = smem_u32(smem);
    int tid = threadIdx.x, lane = tid & 31, wid = tid >> 5;
    int n0 = blockIdx.x * BM;

    int r = tid >> 1, kk = (tid & 1) * 32;
    const float* xrow = x + (size_t)(n0 + r) * H + kk;
    uint32_t a_hi_st = sb + SM_A_HI + (uint32_t)r * AST + (uint32_t)kk * 2u;
    uint32_t a_lo_st = sb + SM_A_LO + (uint32_t)r * AST + (uint32_t)kk * 2u;

    int m0 = wid * 16;
    uint32_t a_ld_off = (uint32_t)(m0 + (lane & 15)) * AST + (uint32_t)((lane >> 4) & 1) * 16u;
    uint32_t b_ld_off = (uint32_t)((lane & 7) + ((lane >> 4) & 1) * 8) * AST
                      + (uint32_t)((lane >> 3) & 1) * 16u;

    float acc[8][4];
#pragma unroll
    for (int i = 0; i < 8; i++)
#pragma unroll
        for (int j = 0; j < 4; j++) acc[i][j] = 0.f;

    float4 cur[8], nxt[8];
#pragma unroll
    for (int i = 0; i < 8; i++) cur[i] = *(const float4*)(xrow + i * 4);

    for (int c = 0; c < 16; c++) {
        if (c < 15) {
#pragma unroll
            for (int i = 0; i < 8; i++) nxt[i] = *(const float4*)(xrow + (c + 1) * 64 + i * 4);
        }
#pragma unroll
        for (int j = 0; j < 2; j++) {
            int idx = tid * 2 + j;
            int n = idx >> 3, seg = idx & 7;
            uint32_t off = (uint32_t)n * AST + (uint32_t)seg * 16u;
            const char* sh = (const char*)g_whi + n * 2048 + c * 128 + seg * 16;
            const char* sl = (const char*)g_wlo + n * 2048 + c * 128 + seg * 16;
            cp16(sb + SM_B_HI + off, sh);
            cp16(sb + SM_B_LO + off, sl);
        }
        asm volatile("cp.async.commit_group;" ::: "memory");

#pragma unroll
        for (int i = 0; i < 8; i++) {
            float4 v = cur[i];
            uint32_t h0, l0, h1, l1;
            cvt_split(v.x, v.y, h0, l0);
            cvt_split(v.z, v.w, h1, l1);
            sts32(a_hi_st + i * 8u, h0);      sts32(a_lo_st + i * 8u, l0);
            sts32(a_hi_st + i * 8u + 4u, h1); sts32(a_lo_st + i * 8u + 4u, l1);
        }
        asm volatile("cp.async.wait_group 0;" ::: "memory");
        __syncthreads();

#pragma unroll
        for (int kt = 0; kt < 4; kt++) {
            uint32_t ko = (uint32_t)kt * 32u;
            uint32_t ah[4], al[4];
            ldm_x4(ah, sb + SM_A_HI + a_ld_off + ko);
            ldm_x4(al, sb + SM_A_LO + a_ld_off + ko);
#pragma unroll
            for (int np = 0; np < 4; np++) {
                uint32_t noff = (uint32_t)np * 16u * AST;
                uint32_t bh[4], bl[4];
                ldm_x4(bh, sb + SM_B_HI + b_ld_off + noff + ko);
                ldm_x4(bl, sb + SM_B_LO + b_ld_off + noff + ko);
                mma16816(acc[2 * np],     ah, bh);
                mma16816(acc[2 * np + 1], ah, bh + 2);
                mma16816(acc[2 * np],     ah, bl);
                mma16816(acc[2 * np + 1], ah, bl + 2);
                mma16816(acc[2 * np],     al, bh);
                mma16816(acc[2 * np + 1], al, bh + 2);
            }
        }
        __syncthreads();
#pragma unroll
        for (int i = 0; i < 8; i++) cur[i] = nxt[i];
    }

    int tok = n0 + m0 + (lane >> 2);
    int ec = 2 * (lane & 3);
#pragma unroll
    for (int nt = 0; nt < 8; nt++) {
        *(float2*)(g_logits + (size_t)tok * E + nt * 8 + ec)       = make_float2(acc[nt][0], acc[nt][1]);
        *(float2*)(g_logits + (size_t)(tok + 8) * E + nt * 8 + ec) = make_float2(acc[nt][2], acc[nt][3]);
    }
}

// ---------------- router: softmax + rank/threshold (1 warp / token) ----------------
__global__ __launch_bounds__(256) void router_kernel(float* __restrict__ out_top1, int N) {
    int gwarp = (blockIdx.x * blockDim.x + threadIdx.x) >> 5;
    int lane  = threadIdx.x & 31;
    if (gwarp >= N) return;
    float* row = g_logits + (size_t)gwarp * E;
    float l0 = row[lane], l1 = row[lane + 32];
    float m = fmaxf(l0, l1);
#pragma unroll
    for (int o = 16; o; o >>= 1) m = fmaxf(m, __shfl_xor_sync(0xFFFFFFFFu, m, o));
    float e0 = expf(l0 - m), e1 = expf(l1 - m);
    float s = e0 + e1;
#pragma unroll
    for (int o = 16; o; o >>= 1) s += __shfl_xor_sync(0xFFFFFFFFu, s, o);
    float p0 = e0 / s, p1 = e1 / s;

    int c0 = 0, c1 = 0;
    float S0 = 0.f, S1 = 0.f;
#pragma unroll
    for (int j = 0; j < 64; j++) {
        float pj = __shfl_sync(0xFFFFFFFFu, (j < 32) ? p0 : p1, j & 31);
        bool gr0 = (pj > p0) || (pj == p0 && j < lane);
        bool gr1 = (pj > p1) || (pj == p1 && j < lane + 32);
        if (gr0) { c0++; S0 += pj; }
        if (gr1) { c1++; S1 += pj; }
    }
    bool a0 = (S0 < 0.9f), a1 = (S1 < 0.9f);
    unsigned k0 = a0 ? mono_key(p0 - (float)(c0 + 1)) : 0u;
    unsigned k1 = a1 ? mono_key(p1 - (float)(c1 + 1)) : 0u;
    g_keys[(size_t)gwarp * E + lane]      = k0;
    g_keys[(size_t)gwarp * E + lane + 32] = k1;
    row[lane]      = p0;   // overwrite logits with probs
    row[lane + 32] = p1;
    if (a0) { int pos = atomicAdd(&g_cnt[lane], 1);      g_lists[(size_t)lane * MAXN + pos] = k0; }
    if (a1) { int pos = atomicAdd(&g_cnt[lane + 32], 1); g_lists[(size_t)(lane + 32) * MAXN + pos] = k1; }
    if (c0 == 0) {
        out_top1[gwarp] = (float)lane;
        atomicAdd(&g_fi[lane], 1.f); atomicAdd(&g_pi[lane], p0);
    }
    if (c1 == 0) {
        out_top1[gwarp] = (float)(lane + 32);
        atomicAdd(&g_fi[lane + 32], 1.f); atomicAdd(&g_pi[lane + 32], p1);
    }

    // top-2 gap check -> suspect list for fp64 argmax repair
    unsigned b0 = __ballot_sync(0xFFFFFFFFu, c0 == 0);
    unsigned b1 = __ballot_sync(0xFFFFFFFFu, c1 == 0);
    int etop1 = b0 ? (__ffs(b0) - 1) : (__ffs(b1) + 31);
    unsigned q0 = __ballot_sync(0xFFFFFFFFu, c0 == 1);
    unsigned q1 = __ballot_sync(0xFFFFFFFFu, c1 == 1);
    int etop2 = q0 ? (__ffs(q0) - 1) : (__ffs(q1) + 31);
    float pt1 = __shfl_sync(0xFFFFFFFFu, (etop1 < 32) ? p0 : p1, etop1 & 31);
    float pt2 = __shfl_sync(0xFFFFFFFFu, (etop2 < 32) ? p0 : p1, etop2 & 31);
    if (lane == 0 && (pt1 - pt2) < 1e-3f) {
        int s = atomicAdd(&g_nsus, 1);
        if (s < MAXSUS)
            g_sus[s] = (unsigned)gwarp | ((unsigned)etop1 << 15) | ((unsigned)etop2 << 21);
    }
}

// ---------------- fp64 argmax repair for near-tie tokens ----------------
__global__ __launch_bounds__(64) void repair_kernel(const float* __restrict__ x,
                                                    const float* __restrict__ w,
                                                    float* __restrict__ out_top1) {
    __shared__ double sa[64], sb[64];
    int n = g_nsus;
    if (n > MAXSUS) n = MAXSUS;
    for (int s = blockIdx.x; s < n; s += gridDim.x) {
        unsigned pk = g_sus[s];
        int t  = (int)(pk & 0x7FFFu);
        int ea = (int)((pk >> 15) & 63u);
        int eb = (int)((pk >> 21) & 63u);
        const float* xr = x + (size_t)t * H;
        const float* wa = w + (size_t)ea * H;
        const float* wb = w + (size_t)eb * H;
        double da = 0.0, db = 0.0;
        for (int k = threadIdx.x; k < H; k += 64) {
            double xv = (double)xr[k];
            da += xv * (double)wa[k];
            db += xv * (double)wb[k];
        }
        sa[threadIdx.x] = da; sb[threadIdx.x] = db;
        __syncthreads();
        if (threadIdx.x == 0) {
            double A = 0.0, B = 0.0;
#pragma unroll
            for (int i = 0; i < 64; i++) { A += sa[i]; B += sb[i]; }
            int win = (B > A || (B == A && eb < ea)) ? eb : ea;
            out_top1[t] = (float)win;
        }
        __syncthreads();
    }
}

// ---------------- select: radix C-th largest over compacted list ----------------
__global__ __launch_bounds__(256) void select_kernel(int C) {
    int e = blockIdx.x, tid = threadIdx.x;
    int cnt = g_cnt[e];
    if (cnt <= C) { if (tid == 0) g_thresh[e] = 0u; return; }
    const unsigned* list = g_lists + (size_t)e * MAXN;
    __shared__ unsigned hist[256];
    __shared__ unsigned s_prefix;
    __shared__ int s_rem;
    if (tid == 0) { s_prefix = 0u; s_rem = C; }
    __syncthreads();
    for (int shift = 24; shift >= 0; shift -= 8) {
        hist[tid] = 0u;
        __syncthreads();
        unsigned pref = s_prefix;
        for (int i = tid; i < cnt; i += 256) {
            unsigned key = list[i];
            if ((shift == 24) || ((key >> (shift + 8)) == pref)) {
                unsigned d = (key >> shift) & 0xFFu;
                unsigned act = __activemask();
                unsigned peers = __match_any_sync(act, d);
                if ((tid & 31) == (__ffs(peers) - 1)) atomicAdd(&hist[d], __popc(peers));
            }
        }
        __syncthreads();
        if (tid == 0) {
            int rem = s_rem, b = 255;
            while (b > 0 && (int)hist[b] < rem) { rem -= (int)hist[b]; b--; }
            s_prefix = (s_prefix << 8) | (unsigned)b;
            s_rem = rem;
        }
        __syncthreads();
    }
    if (tid == 0) g_thresh[e] = s_prefix;
}

// ---------------- finalize mask + scores (token-major, coalesced) ----------------
__global__ __launch_bounds__(256) void finalize_kernel(float* __restrict__ mask_out,
                                                       float* __restrict__ scores_out) {
    __shared__ unsigned th[64];
    int t = threadIdx.x;
    if (t < 64) th[t] = g_thresh[t];
    __syncthreads();
    size_t base = (size_t)blockIdx.x * 2048 + (size_t)t * 8;
#pragma unroll
    for (int j = 0; j < 2; j++) {
        size_t o = base + (size_t)j * 4;
        uint4  k = *(const uint4*)(g_keys + o);
        float4 p = *(const float4*)(g_logits + o);
        int e0 = (int)(o & 63);
        float4 mo, so;
        bool b0 = k.x && k.x >= th[e0 + 0];
        bool b1 = k.y && k.y >= th[e0 + 1];
        bool b2 = k.z && k.z >= th[e0 + 2];
        bool b3 = k.w && k.w >= th[e0 + 3];
        mo.x = b0 ? 1.f : 0.f; so.x = b0 ? p.x : 0.f;
        mo.y = b1 ? 1.f : 0.f; so.y = b1 ? p.y : 0.f;
        mo.z = b2 ? 1.f : 0.f; so.z = b2 ? p.z : 0.f;
        mo.w = b3 ? 1.f : 0.f; so.w = b3 ? p.w : 0.f;
        *(float4*)(mask_out + o)   = mo;
        *(float4*)(scores_out + o) = so;
    }
}

// ---------------- aux loss ----------------
__global__ void aux_kernel(float* __restrict__ out_aux, int N) {
    int l = threadIdx.x;
    float v = g_fi[l] * g_pi[l] + g_fi[l + 32] * g_pi[l + 32];
#pragma unroll
    for (int o = 16; o; o >>= 1) v += __shfl_xor_sync(0xFFFFFFFFu, v, o);
    if (l == 0) out_aux[0] = (float)E * (v / ((float)N * (float)N)) * 0.01f;
}

// ---------------- launch ----------------
extern "C" void kernel_launch(void* const* d_in, const int* in_sizes, int n_in,
                              void* d_out, int out_size) {
    const float* x = (const float*)d_in[0];
    const float* w = (const float*)d_in[1];
    int N = in_sizes[0] / H;            // 32768
    int C = (N + E - 1) / E;            // capacity (factor 1.0)
    if (C > N) C = N;

    float* out      = (float*)d_out;
    float* mask_out = out;
    float* scr_out  = out + (size_t)N * E;
    float* aux_out  = out + (size_t)2 * N * E;
    float* top1_out = out + (size_t)2 * N * E + 1;

    cudaFuncSetAttribute(gemm_mma_kernel, cudaFuncAttributeMaxDynamicSharedMemorySize, SMEM_BYTES);

    init_kernel<<<1, 64>>>();
    convert_w_kernel<<<(E * H + 255) / 256, 256>>>(w);
    gemm_mma_kernel<<<N / BM, 256, SMEM_BYTES>>>(x);
    router_kernel<<<(N * 32) / 256, 256>>>(top1_out, N);
    repair_kernel<<<256, 64>>>(x, w, top1_out);
    select_kernel<<<E, 256>>>(C);
    finalize_kernel<<<(N * E) / 2048, 256>>>(mask_out, scr_out);
    aux_kernel<<<1, 32>>>(aux_out, N);
}

// round 6
// speedup vs baseline: 2.3928x; 2.3928x over previous
#include <cuda_runtime.h>
#include <cuda_bf16.h>
#include <math.h>
#include <stdint.h>

#define H 1024
#define E 64
#define MAXN 32768
#define BM 128
#define AST 144u          // padded smem row stride (bytes): 64 bf16 + 16B pad
#define MAXSUS 8192
#define SEG 4             // segments per expert in hist pass

// smem layout (bytes) for gemm
#define SM_A_HI 0u
#define SM_A_LO 18432u
#define SM_B_HI 36864u
#define SM_B_LO 46080u
#define SMEM_BYTES 55296

// ---------------- scratch (no allocation allowed) ----------------
__device__ float         g_logits[(size_t)MAXN * E];   // logits -> probs (in place)
__device__ unsigned      g_keys[(size_t)MAXN * E];     // token-major mono keys (0 = unassigned)
__device__ unsigned      g_keyT[(size_t)E * MAXN];     // expert-major keys for select
__device__ unsigned      g_hist[E][2048];
__device__ unsigned      g_prefix[E];
__device__ unsigned      g_rem[E];
__device__ unsigned      g_thresh[E];
__device__ __align__(256) __nv_bfloat16 g_whi[E * H];
__device__ __align__(256) __nv_bfloat16 g_wlo[E * H];
__device__ float         g_fi[E];
__device__ float         g_pi[E];
__device__ int           g_nsus;
__device__ unsigned      g_sus[MAXSUS];

__device__ __forceinline__ unsigned mono_key(float f) {
    unsigned u = __float_as_uint(f);
    return (u & 0x80000000u) ? ~u : (u | 0x80000000u);
}

static __device__ __forceinline__ uint32_t smem_u32(const void* p) {
    uint32_t a;
    asm("{ .reg .u64 t; cvta.to.shared.u64 t, %1; cvt.u32.u64 %0, t; }" : "=r"(a) : "l"(p));
    return a;
}
static __device__ __forceinline__ void cp16(uint32_t dst, const void* src) {
    asm volatile("cp.async.ca.shared.global [%0], [%1], 16;" :: "r"(dst), "l"(src) : "memory");
}
static __device__ __forceinline__ void sts32(uint32_t addr, uint32_t v) {
    asm volatile("st.shared.b32 [%0], %1;" :: "r"(addr), "r"(v) : "memory");
}
static __device__ __forceinline__ void ldm_x4(uint32_t* r, uint32_t addr) {
    asm volatile("ldmatrix.sync.aligned.m8n8.x4.shared.b16 {%0,%1,%2,%3}, [%4];"
                 : "=r"(r[0]), "=r"(r[1]), "=r"(r[2]), "=r"(r[3]) : "r"(addr));
}
static __device__ __forceinline__ void mma16816(float* c, const uint32_t* a, const uint32_t* b) {
    asm volatile("mma.sync.aligned.m16n8k16.row.col.f32.bf16.bf16.f32 "
                 "{%0,%1,%2,%3}, {%4,%5,%6,%7}, {%8,%9}, {%0,%1,%2,%3};"
                 : "+f"(c[0]), "+f"(c[1]), "+f"(c[2]), "+f"(c[3])
                 : "r"(a[0]), "r"(a[1]), "r"(a[2]), "r"(a[3]), "r"(b[0]), "r"(b[1]));
}
static __device__ __forceinline__ void cvt_split(float a, float b, uint32_t& hi, uint32_t& lo) {
    __nv_bfloat162 h = __floats2bfloat162_rn(a, b);
    hi = *reinterpret_cast<uint32_t*>(&h);
    __nv_bfloat162 l = __floats2bfloat162_rn(a - __low2float(h), b - __high2float(h));
    lo = *reinterpret_cast<uint32_t*>(&l);
}

// ---------------- init ----------------
__global__ void init_kernel(int C) {
    int t = threadIdx.x;
    if (t < E) {
        g_fi[t] = 0.f; g_pi[t] = 0.f;
        g_prefix[t] = 0u; g_rem[t] = (unsigned)C;
    }
    if (t == 0) g_nsus = 0;
}

// ---------------- convert gate_w to bf16 hi/lo ----------------
__global__ __launch_bounds__(256) void convert_w_kernel(const float* __restrict__ w) {
    int i = blockIdx.x * blockDim.x + threadIdx.x;
    if (i < E * H) {
        float v = w[i];
        __nv_bfloat16 h = __float2bfloat16(v);
        g_whi[i] = h;
        g_wlo[i] = __float2bfloat16(v - __bfloat162float(h));
    }
}

// ---------------- HMMA GEMM: 128 tokens x 64 experts / block, 3-pass bf16 split ----------------
__global__ __launch_bounds__(256, 2) void gemm_mma_kernel(const float* __restrict__ x) {
    extern __shared__ __align__(16) char smem[];
    uint32_t sb = smem_u32(smem);
    int tid = threadIdx.x, lane = tid & 31, wid = tid >> 5;
    int n0 = blockIdx.x * BM;

    int r = tid >> 1, kk = (tid & 1) * 32;
    const float* xrow = x + (size_t)(n0 + r) * H + kk;
    uint32_t a_hi_st = sb + SM_A_HI + (uint32_t)r * AST + (uint32_t)kk * 2u;
    uint32_t a_lo_st = sb + SM_A_LO + (uint32_t)r * AST + (uint32_t)kk * 2u;

    int m0 = wid * 16;
    uint32_t a_ld_off = (uint32_t)(m0 + (lane & 15)) * AST + (uint32_t)((lane >> 4) & 1) * 16u;
    uint32_t b_ld_off = (uint32_t)((lane & 7) + ((lane >> 4) & 1) * 8) * AST
                      + (uint32_t)((lane >> 3) & 1) * 16u;

    float acc[8][4];
#pragma unroll
    for (int i = 0; i < 8; i++)
#pragma unroll
        for (int j = 0; j < 4; j++) acc[i][j] = 0.f;

    float4 cur[8], nxt[8];
#pragma unroll
    for (int i = 0; i < 8; i++) cur[i] = *(const float4*)(xrow + i * 4);

    for (int c = 0; c < 16; c++) {
        if (c < 15) {
#pragma unroll
            for (int i = 0; i < 8; i++) nxt[i] = *(const float4*)(xrow + (c + 1) * 64 + i * 4);
        }
#pragma unroll
        for (int j = 0; j < 2; j++) {
            int idx = tid * 2 + j;
            int n = idx >> 3, seg = idx & 7;
            uint32_t off = (uint32_t)n * AST + (uint32_t)seg * 16u;
            const char* sh = (const char*)g_whi + n * 2048 + c * 128 + seg * 16;
            const char* sl = (const char*)g_wlo + n * 2048 + c * 128 + seg * 16;
            cp16(sb + SM_B_HI + off, sh);
            cp16(sb + SM_B_LO + off, sl);
        }
        asm volatile("cp.async.commit_group;" ::: "memory");

#pragma unroll
        for (int i = 0; i < 8; i++) {
            float4 v = cur[i];
            uint32_t h0, l0, h1, l1;
            cvt_split(v.x, v.y, h0, l0);
            cvt_split(v.z, v.w, h1, l1);
            sts32(a_hi_st + i * 8u, h0);      sts32(a_lo_st + i * 8u, l0);
            sts32(a_hi_st + i * 8u + 4u, h1); sts32(a_lo_st + i * 8u + 4u, l1);
        }
        asm volatile("cp.async.wait_group 0;" ::: "memory");
        __syncthreads();

#pragma unroll
        for (int kt = 0; kt < 4; kt++) {
            uint32_t ko = (uint32_t)kt * 32u;
            uint32_t ah[4], al[4];
            ldm_x4(ah, sb + SM_A_HI + a_ld_off + ko);
            ldm_x4(al, sb + SM_A_LO + a_ld_off + ko);
#pragma unroll
            for (int np = 0; np < 4; np++) {
                uint32_t noff = (uint32_t)np * 16u * AST;
                uint32_t bh[4], bl[4];
                ldm_x4(bh, sb + SM_B_HI + b_ld_off + noff + ko);
                ldm_x4(bl, sb + SM_B_LO + b_ld_off + noff + ko);
                mma16816(acc[2 * np],     ah, bh);
                mma16816(acc[2 * np + 1], ah, bh + 2);
                mma16816(acc[2 * np],     ah, bl);
                mma16816(acc[2 * np + 1], ah, bl + 2);
                mma16816(acc[2 * np],     al, bh);
                mma16816(acc[2 * np + 1], al, bh + 2);
            }
        }
        __syncthreads();
#pragma unroll
        for (int i = 0; i < 8; i++) cur[i] = nxt[i];
    }

    int tok = n0 + m0 + (lane >> 2);
    int ec = 2 * (lane & 3);
#pragma unroll
    for (int nt = 0; nt < 8; nt++) {
        *(float2*)(g_logits + (size_t)tok * E + nt * 8 + ec)       = make_float2(acc[nt][0], acc[nt][1]);
        *(float2*)(g_logits + (size_t)(tok + 8) * E + nt * 8 + ec) = make_float2(acc[nt][2], acc[nt][3]);
    }
}

// ---------------- router: softmax + rank/threshold (1 warp / token) ----------------
__global__ __launch_bounds__(256) void router_kernel(float* __restrict__ out_top1, int N) {
    int gwarp = (blockIdx.x * blockDim.x + threadIdx.x) >> 5;
    int lane  = threadIdx.x & 31;
    if (gwarp >= N) return;
    float* row = g_logits + (size_t)gwarp * E;
    float l0 = row[lane], l1 = row[lane + 32];
    float m = fmaxf(l0, l1);
#pragma unroll
    for (int o = 16; o; o >>= 1) m = fmaxf(m, __shfl_xor_sync(0xFFFFFFFFu, m, o));
    float e0 = expf(l0 - m), e1 = expf(l1 - m);
    float s = e0 + e1;
#pragma unroll
    for (int o = 16; o; o >>= 1) s += __shfl_xor_sync(0xFFFFFFFFu, s, o);
    float p0 = e0 / s, p1 = e1 / s;

    int c0 = 0, c1 = 0;
    float S0 = 0.f, S1 = 0.f;
#pragma unroll
    for (int j = 0; j < 64; j++) {
        float pj = __shfl_sync(0xFFFFFFFFu, (j < 32) ? p0 : p1, j & 31);
        bool gr0 = (pj > p0) || (pj == p0 && j < lane);
        bool gr1 = (pj > p1) || (pj == p1 && j < lane + 32);
        if (gr0) { c0++; S0 += pj; }
        if (gr1) { c1++; S1 += pj; }
    }
    bool a0 = (S0 < 0.9f), a1 = (S1 < 0.9f);
    unsigned k0 = a0 ? mono_key(p0 - (float)(c0 + 1)) : 0u;
    unsigned k1 = a1 ? mono_key(p1 - (float)(c1 + 1)) : 0u;
    g_keys[(size_t)gwarp * E + lane]      = k0;
    g_keys[(size_t)gwarp * E + lane + 32] = k1;
    g_keyT[(size_t)lane * N + gwarp]        = k0;
    g_keyT[(size_t)(lane + 32) * N + gwarp] = k1;
    row[lane]      = p0;   // overwrite logits with probs
    row[lane + 32] = p1;
    if (c0 == 0) {
        out_top1[gwarp] = (float)lane;
        atomicAdd(&g_fi[lane], 1.f); atomicAdd(&g_pi[lane], p0);
    }
    if (c1 == 0) {
        out_top1[gwarp] = (float)(lane + 32);
        atomicAdd(&g_fi[lane + 32], 1.f); atomicAdd(&g_pi[lane + 32], p1);
    }

    // near-tie detection on LOGITS (error bound ~1e-6, margin 100x)
    unsigned b0 = __ballot_sync(0xFFFFFFFFu, c0 == 0);
    unsigned b1 = __ballot_sync(0xFFFFFFFFu, c1 == 0);
    int etop1 = b0 ? (__ffs(b0) - 1) : (__ffs(b1) + 31);
    unsigned q0 = __ballot_sync(0xFFFFFFFFu, c0 == 1);
    unsigned q1 = __ballot_sync(0xFFFFFFFFu, c1 == 1);
    int etop2 = q0 ? (__ffs(q0) - 1) : (__ffs(q1) + 31);
    float lt1 = __shfl_sync(0xFFFFFFFFu, (etop1 < 32) ? l0 : l1, etop1 & 31);
    float lt2 = __shfl_sync(0xFFFFFFFFu, (etop2 < 32) ? l0 : l1, etop2 & 31);
    if (lane == 0 && (lt1 - lt2) < 1e-4f) {
        int sp = atomicAdd(&g_nsus, 1);
        if (sp < MAXSUS)
            g_sus[sp] = (unsigned)gwarp | ((unsigned)etop1 << 15) | ((unsigned)etop2 << 21);
    }
}

// ---------------- fp64 argmax repair: one warp per suspect ----------------
__global__ __launch_bounds__(128) void repair_kernel(const float* __restrict__ x,
                                                     const float* __restrict__ w,
                                                     float* __restrict__ out_top1) {
    int n = g_nsus;
    if (n > MAXSUS) n = MAXSUS;
    int nwarp = gridDim.x * (blockDim.x >> 5);
    int gw = blockIdx.x * (blockDim.x >> 5) + (threadIdx.x >> 5);
    int lane = threadIdx.x & 31;
    for (int s = gw; s < n; s += nwarp) {
        unsigned pk = g_sus[s];
        int t  = (int)(pk & 0x7FFFu);
        int ea = (int)((pk >> 15) & 63u);
        int eb = (int)((pk >> 21) & 63u);
        const float* xr = x + (size_t)t * H;
        const float* wa = w + (size_t)ea * H;
        const float* wb = w + (size_t)eb * H;
        double da = 0.0, db = 0.0;
        for (int k = lane; k < H; k += 32) {
            double xv = (double)xr[k];
            da += xv * (double)wa[k];
            db += xv * (double)wb[k];
        }
#pragma unroll
        for (int o = 16; o; o >>= 1) {
            da += __shfl_xor_sync(0xFFFFFFFFu, da, o);
            db += __shfl_xor_sync(0xFFFFFFFFu, db, o);
        }
        if (lane == 0) {
            int win = (db > da || (db == da && eb < ea)) ? eb : ea;
            out_top1[t] = (float)win;
        }
    }
}

// ---------------- select pass kernels: 3-pass 11/11/10-bit radix ----------------
__global__ __launch_bounds__(256) void hist_kernel(int N, int pass) {
    int e = blockIdx.x / SEG, seg = blockIdx.x % SEG;
    __shared__ unsigned h[2048];
    int tid = threadIdx.x;
    for (int i = tid; i < 2048; i += 256) h[i] = 0u;
    __syncthreads();
    unsigned pref = g_prefix[e];
    const uint4* col = (const uint4*)(g_keyT + (size_t)e * N + (size_t)seg * (N / SEG));
    int n4 = (N / SEG) >> 2;
    for (int i = tid; i < n4; i += 256) {
        uint4 kv = col[i];
        unsigned ks[4] = {kv.x, kv.y, kv.z, kv.w};
#pragma unroll
        for (int j = 0; j < 4; j++) {
            unsigned k = ks[j];
            if (!k) continue;                 // unassigned
            bool mt; unsigned d;
            if (pass == 0)      { mt = true;                 d = k >> 21; }
            else if (pass == 1) { mt = ((k >> 21) == pref);  d = (k >> 10) & 0x7FFu; }
            else                { mt = ((k >> 10) == pref);  d = k & 0x3FFu; }
            if (mt) {
                unsigned act = __activemask();
                unsigned peers = __match_any_sync(act, d);
                int ldr = __ffs(peers) - 1;
                if ((tid & 31) == ldr) atomicAdd(&h[d], __popc(peers));
            }
        }
    }
    __syncthreads();
    for (int i = tid; i < 2048; i += 256) if (h[i]) atomicAdd(&g_hist[e][i], h[i]);
}

__global__ __launch_bounds__(256) void scan_kernel(int pass) {
    int e = blockIdx.x, t = threadIdx.x;
    __shared__ unsigned part[256], incl[256];
    __shared__ int found;
    if (t == 0) found = 0;
    unsigned mybin[8];
    unsigned s = 0;
#pragma unroll
    for (int j = 0; j < 8; j++) { mybin[j] = g_hist[e][2047 - (8 * t + j)]; s += mybin[j]; }
    part[t] = s; incl[t] = s;
    __syncthreads();
    for (int off = 1; off < 256; off <<= 1) {
        unsigned v = (t >= off) ? incl[t - off] : 0u;
        __syncthreads();
        incl[t] += v;
        __syncthreads();
    }
    unsigned rem = g_rem[e];
    unsigned ex = incl[t] - part[t];
    if (ex < rem && incl[t] >= rem) {
        unsigned r = rem - ex;
        int digit = 0;
#pragma unroll
        for (int j = 0; j < 8; j++) {
            unsigned cnt = mybin[j];
            if (cnt >= r) { digit = 2047 - (8 * t + j); break; }
            r -= cnt;
        }
        if (pass == 0)      g_prefix[e] = (unsigned)digit;
        else if (pass == 1) g_prefix[e] = (g_prefix[e] << 11) | (unsigned)digit;
        else                g_thresh[e] = (g_prefix[e] << 10) | (unsigned)digit;
        g_rem[e] = r;
        found = 1;
    }
    __syncthreads();
    if (!found && t == 0) {
        // fewer assigned than capacity: keep every assigned token
        if (pass == 2) g_thresh[e] = 1u;
        else g_rem[e] = 0xFFFFFFFFu;
    }
    // zero hist for next pass / next run
#pragma unroll
    for (int j = 0; j < 8; j++) g_hist[e][t * 8 + j] = 0u;
}

// ---------------- finalize mask + scores (token-major, coalesced) ----------------
__global__ __launch_bounds__(256) void finalize_kernel(float* __restrict__ mask_out,
                                                       float* __restrict__ scores_out) {
    __shared__ unsigned th[64];
    int t = threadIdx.x;
    if (t < 64) th[t] = g_thresh[t];
    __syncthreads();
    size_t base = (size_t)blockIdx.x * 2048 + (size_t)t * 8;
#pragma unroll
    for (int j = 0; j < 2; j++) {
        size_t o = base + (size_t)j * 4;
        uint4  k = *(const uint4*)(g_keys + o);
        float4 p = *(const float4*)(g_logits + o);
        int e0 = (int)(o & 63);
        float4 mo, so;
        bool b0 = k.x && k.x >= th[e0 + 0];
        bool b1 = k.y && k.y >= th[e0 + 1];
        bool b2 = k.z && k.z >= th[e0 + 2];
        bool b3 = k.w && k.w >= th[e0 + 3];
        mo.x = b0 ? 1.f : 0.f; so.x = b0 ? p.x : 0.f;
        mo.y = b1 ? 1.f : 0.f; so.y = b1 ? p.y : 0.f;
        mo.z = b2 ? 1.f : 0.f; so.z = b2 ? p.z : 0.f;
        mo.w = b3 ? 1.f : 0.f; so.w = b3 ? p.w : 0.f;
        *(float4*)(mask_out + o)   = mo;
        *(float4*)(scores_out + o) = so;
    }
}

// ---------------- aux loss ----------------
__global__ void aux_kernel(float* __restrict__ out_aux, int N) {
    int l = threadIdx.x;
    float v = g_fi[l] * g_pi[l] + g_fi[l + 32] * g_pi[l + 32];
#pragma unroll
    for (int o = 16; o; o >>= 1) v += __shfl_xor_sync(0xFFFFFFFFu, v, o);
    if (l == 0) out_aux[0] = (float)E * (v / ((float)N * (float)N)) * 0.01f;
}

// ---------------- launch ----------------
extern "C" void kernel_launch(void* const* d_in, const int* in_sizes, int n_in,
                              void* d_out, int out_size) {
    const float* x = (const float*)d_in[0];
    const float* w = (const float*)d_in[1];
    int N = in_sizes[0] / H;            // 32768
    int C = (N + E - 1) / E;            // capacity (factor 1.0)
    if (C > N) C = N;

    float* out      = (float*)d_out;
    float* mask_out = out;
    float* scr_out  = out + (size_t)N * E;
    float* aux_out  = out + (size_t)2 * N * E;
    float* top1_out = out + (size_t)2 * N * E + 1;

    cudaFuncSetAttribute(gemm_mma_kernel, cudaFuncAttributeMaxDynamicSharedMemorySize, SMEM_BYTES);

    init_kernel<<<1, 64>>>(C);
    convert_w_kernel<<<(E * H + 255) / 256, 256>>>(w);
    gemm_mma_kernel<<<N / BM, 256, SMEM_BYTES>>>(x);
    router_kernel<<<(N * 32) / 256, 256>>>(top1_out, N);
    repair_kernel<<<64, 128>>>(x, w, top1_out);
    for (int p = 0; p < 3; p++) {
        hist_kernel<<<E * SEG, 256>>>(N, p);
        scan_kernel<<<E, 256>>>(p);
    }
    finalize_kernel<<<(N * E) / 2048, 256>>>(mask_out, scr_out);
    aux_kernel<<<1, 32>>>(aux_out, N);
}